// round 15
// baseline (speedup 1.0000x reference)
#include <cuda_runtime.h>
#include <cstddef>
#include <cstdint>

#define N_NODES 50000
#define C_DIM   64
#define HID_DIM 128
#define R_DIM   16
#define B_DIM   2
#define L_DIM   12
#define E_EDGES 1600000
#define T_DIM   8
#define M_ROWS  (B_DIM * N_NODES)   // 100000

// Tables laid out [node][batch][16 floats]: one node = one 128B line.
__device__ __align__(128) float4 g_a[M_ROWS * 4];
__device__ __align__(128) float4 g_b[M_ROWS * 4];

__device__ __forceinline__ uint32_t f2tf(float x) {
    uint32_t r;
    asm("cvt.rna.tf32.f32 %0, %1;" : "=r"(r) : "f"(x));
    return r;
}

__device__ __forceinline__ void mma_tf32(float* d, uint32_t a0, uint32_t a1,
                                         uint32_t a2, uint32_t a3,
                                         uint32_t b0, uint32_t b1) {
    asm volatile(
        "mma.sync.aligned.m16n8k8.row.col.f32.tf32.tf32.f32 "
        "{%0,%1,%2,%3}, {%4,%5,%6,%7}, {%8,%9}, {%0,%1,%2,%3};"
        : "+f"(d[0]), "+f"(d[1]), "+f"(d[2]), "+f"(d[3])
        : "r"(a0), "r"(a1), "r"(a2), "r"(a3), "r"(b0), "r"(b1));
}

// ---------------------------------------------------------------------------
// Kernel 1: tf32 tensor-core MLP — exact R11 version (best measured 44.6us).
// M128 tile, 256 threads, one weight set per blockIdx.y.
// ---------------------------------------------------------------------------
#define SH  68
#define SW1 136
#define SHD 132
#define SW2 20

__global__ __launch_bounds__(256, 2)
void mlp_kernel(const float* __restrict__ X,
                const float* __restrict__ W1s, const float* __restrict__ b1s,
                const float* __restrict__ W2s, const float* __restrict__ b2s,
                const float* __restrict__ W1d, const float* __restrict__ b1d,
                const float* __restrict__ W2d, const float* __restrict__ b2d)
{
    extern __shared__ float sh[];
    float* W2sm = sh;                     // [128][20]
    float* Hsm  = sh + 128 * SW2;         // [128][68]
    float* W1sm = Hsm + 128 * SH;         // [64][136]
    float* Hid  = Hsm;                    // [128][132] alias

    const int tid  = threadIdx.x;
    const int lane = tid & 31;
    const int warp = tid >> 5;
    const int g    = lane >> 2;
    const int t    = lane & 3;
    const int m0   = blockIdx.x * 128;
    const int set  = blockIdx.y;

    const float* W1 = set ? W1d : W1s;
    const float* b1 = set ? b1d : b1s;
    const float* W2 = set ? W2d : W2s;
    const float* b2 = set ? b2d : b2s;
    float4* outTab  = set ? g_b : g_a;

    uint32_t* Hu  = (uint32_t*)Hsm;
    uint32_t* W1u = (uint32_t*)W1sm;
    uint32_t* W2u = (uint32_t*)W2sm;
    uint32_t* Du  = (uint32_t*)Hid;

    #pragma unroll
    for (int u = 0; u < 8; u++) {
        int id = tid + 256 * u;
        int r  = id >> 4, cg = id & 15;
        int m  = m0 + r;
        float4 v = make_float4(0.f, 0.f, 0.f, 0.f);
        if (m < M_ROWS) {
            int b = m / N_NODES;
            int n = m - b * N_NODES;
            v = *(const float4*)&X[(((size_t)b * T_DIM + (T_DIM - 1)) * N_NODES + n) * C_DIM + cg * 4];
        }
        uint4 w; w.x = f2tf(v.x); w.y = f2tf(v.y); w.z = f2tf(v.z); w.w = f2tf(v.w);
        *(uint4*)&Hu[r * SH + cg * 4] = w;
    }
    #pragma unroll
    for (int u = 0; u < 8; u++) {
        int id = tid + 256 * u;
        int k = id >> 5, ng = id & 31;
        float4 v = *(const float4*)&W1[k * 128 + ng * 4];
        uint4 w; w.x = f2tf(v.x); w.y = f2tf(v.y); w.z = f2tf(v.z); w.w = f2tf(v.w);
        *(uint4*)&W1u[k * SW1 + ng * 4] = w;
    }
    #pragma unroll
    for (int u = 0; u < 2; u++) {
        int id = tid + 256 * u;
        int k = id >> 2, rg = id & 3;
        float4 v = *(const float4*)&W2[k * 16 + rg * 4];
        uint4 w; w.x = f2tf(v.x); w.y = f2tf(v.y); w.z = f2tf(v.z); w.w = f2tf(v.w);
        *(uint4*)&W2u[k * SW2 + rg * 4] = w;
    }
    __syncthreads();

    const int mr = warp >> 1;
    const int nc = warp & 1;
    float acc[2][8][4];
    #pragma unroll
    for (int mt = 0; mt < 2; mt++)
        #pragma unroll
        for (int nt = 0; nt < 8; nt++)
            #pragma unroll
            for (int i = 0; i < 4; i++) acc[mt][nt][i] = 0.0f;

    #pragma unroll
    for (int kk = 0; kk < 8; kk++) {
        const int k0 = kk * 8;
        uint32_t a[2][4];
        #pragma unroll
        for (int mt = 0; mt < 2; mt++) {
            int row = mr * 32 + mt * 16;
            a[mt][0] = Hu[(row + g)     * SH + k0 + t];
            a[mt][1] = Hu[(row + g + 8) * SH + k0 + t];
            a[mt][2] = Hu[(row + g)     * SH + k0 + t + 4];
            a[mt][3] = Hu[(row + g + 8) * SH + k0 + t + 4];
        }
        #pragma unroll
        for (int nt = 0; nt < 8; nt++) {
            int n = nc * 64 + nt * 8 + g;
            uint32_t b0 = W1u[(k0 + t)     * SW1 + n];
            uint32_t b1v = W1u[(k0 + t + 4) * SW1 + n];
            mma_tf32(acc[0][nt], a[0][0], a[0][1], a[0][2], a[0][3], b0, b1v);
            mma_tf32(acc[1][nt], a[1][0], a[1][1], a[1][2], a[1][3], b0, b1v);
        }
    }
    __syncthreads();

    #pragma unroll
    for (int nt = 0; nt < 8; nt++) {
        int ncol = nc * 64 + nt * 8 + t * 2;
        float2 bb = __ldg((const float2*)&b1[ncol]);
        #pragma unroll
        for (int mt = 0; mt < 2; mt++) {
            int row = mr * 32 + mt * 16;
            float v0 = acc[mt][nt][0] + bb.x; v0 = v0 > 0.f ? v0 : 0.f;
            float v1 = acc[mt][nt][1] + bb.y; v1 = v1 > 0.f ? v1 : 0.f;
            float v2 = acc[mt][nt][2] + bb.x; v2 = v2 > 0.f ? v2 : 0.f;
            float v3 = acc[mt][nt][3] + bb.y; v3 = v3 > 0.f ? v3 : 0.f;
            uint2 w01; w01.x = f2tf(v0); w01.y = f2tf(v1);
            uint2 w23; w23.x = f2tf(v2); w23.y = f2tf(v3);
            *(uint2*)&Du[(row + g)     * SHD + ncol] = w01;
            *(uint2*)&Du[(row + g + 8) * SHD + ncol] = w23;
        }
    }
    __syncthreads();

    {
        float acc2[2][4];
        #pragma unroll
        for (int nt = 0; nt < 2; nt++)
            #pragma unroll
            for (int i = 0; i < 4; i++) acc2[nt][i] = 0.0f;

        const int rowb = warp * 16;
        #pragma unroll
        for (int kk = 0; kk < 16; kk++) {
            const int k0 = kk * 8;
            uint32_t a0 = Du[(rowb + g)     * SHD + k0 + t];
            uint32_t a1 = Du[(rowb + g + 8) * SHD + k0 + t];
            uint32_t a2 = Du[(rowb + g)     * SHD + k0 + t + 4];
            uint32_t a3 = Du[(rowb + g + 8) * SHD + k0 + t + 4];
            #pragma unroll
            for (int nt = 0; nt < 2; nt++) {
                uint32_t b0 = W2u[(k0 + t)     * SW2 + nt * 8 + g];
                uint32_t b1v = W2u[(k0 + t + 4) * SW2 + nt * 8 + g];
                mma_tf32(acc2[nt], a0, a1, a2, a3, b0, b1v);
            }
        }

        #pragma unroll
        for (int nt = 0; nt < 2; nt++) {
            int r0 = nt * 8 + t * 2;
            float2 bb = __ldg((const float2*)&b2[r0]);
            int m = m0 + rowb + g;
            if (m < M_ROWS) {
                int b = m / N_NODES, n = m - b * N_NODES;
                float2 v; v.x = acc2[nt][0] + bb.x; v.y = acc2[nt][1] + bb.y;
                *(float2*)((float*)outTab + ((size_t)n * 2 + b) * 16 + r0) = v;
            }
            m = m0 + rowb + g + 8;
            if (m < M_ROWS) {
                int b = m / N_NODES, n = m - b * N_NODES;
                float2 v; v.x = acc2[nt][2] + bb.x; v.y = acc2[nt][3] + bb.y;
                *(float2*)((float*)outTab + ((size_t)n * 2 + b) * 16 + r0) = v;
            }
        }
    }
}

// ---------------------------------------------------------------------------
// Kernel 2: edge scoring. 512 threads / 256 edges; thread = (edge, batch).
// Fused product-gather (unchanged); compute threads hold only p[16]
// (regs ~40 -> 3 CTAs/SM = 75% occ). Warps 0-7 = batch 0, 8-15 = batch 1.
// ---------------------------------------------------------------------------
#define EPB 256
#define PSTRIDE 9     // float4 per edge in p-stage (8 + 1 pad)

__global__ __launch_bounds__(512)
void edge_kernel(const int* __restrict__ eidx,
                 const float* __restrict__ gamma,
                 float* __restrict__ out)
{
    __shared__ float4 pst[EPB * PSTRIDE];    // 36,864 B
    __shared__ int    sIJ[2 * EPB];
    __shared__ float  g[L_DIM * R_DIM];

    const int tid = threadIdx.x;
    const long long e0 = (long long)blockIdx.x * EPB;

    if (tid < EPB) sIJ[tid] = eidx[e0 + tid];
    else           sIJ[tid] = eidx[(size_t)E_EDGES + e0 + (tid - EPB)];
    if (tid < L_DIM * R_DIM) g[tid] = gamma[tid];
    __syncthreads();

    // Fused gather+product: 2048 (edge,sub) pairs, 4 per thread.
    {
        float4 pr[4];
        int    dst[4];
        #pragma unroll
        for (int u = 0; u < 4; u++) {
            int gid  = tid + 512 * u;
            int edge = gid >> 3;
            int sub  = gid & 7;            // bb*4 + q
            int nI   = sIJ[edge];
            int nJ   = sIJ[EPB + edge];
            float4 av = g_a[(size_t)nI * 8 + sub];
            float4 bv = g_b[(size_t)nJ * 8 + sub];
            float4 p;
            p.x = av.x * bv.x; p.y = av.y * bv.y;
            p.z = av.z * bv.z; p.w = av.w * bv.w;
            pr[u]  = p;
            dst[u] = edge * PSTRIDE + sub;
        }
        #pragma unroll
        for (int u = 0; u < 4; u++) pst[dst[u]] = pr[u];
    }
    __syncthreads();

    // Compute: thread = (bb = tid>>8, e = tid&255). 16-reg p[].
    {
        const int bb = tid >> 8;
        const int e  = tid & 255;
        const float4* base = pst + e * PSTRIDE + bb * 4;

        float p[16];
        #pragma unroll
        for (int q = 0; q < 4; q++) {
            float4 v = base[q];
            p[q * 4 + 0] = v.x; p[q * 4 + 1] = v.y;
            p[q * 4 + 2] = v.z; p[q * 4 + 3] = v.w;
        }

        float* o = out + (size_t)bb * L_DIM * E_EDGES + e0 + e;
        #pragma unroll
        for (int l = 0; l < L_DIM; l++) {
            const float4* gr = (const float4*)&g[l * R_DIM];
            float4 g0 = gr[0], g1 = gr[1], g2 = gr[2], g3 = gr[3];
            float s = g0.x * p[0]  + g0.y * p[1]  + g0.z * p[2]  + g0.w * p[3]
                    + g1.x * p[4]  + g1.y * p[5]  + g1.z * p[6]  + g1.w * p[7]
                    + g2.x * p[8]  + g2.y * p[9]  + g2.z * p[10] + g2.w * p[11]
                    + g3.x * p[12] + g3.y * p[13] + g3.z * p[14] + g3.w * p[15];
            __stcs(o + (size_t)l * E_EDGES, s);
        }
    }
}

// ---------------------------------------------------------------------------
// Launch
// ---------------------------------------------------------------------------
extern "C" void kernel_launch(void* const* d_in, const int* in_sizes, int n_in,
                              void* d_out, int out_size)
{
    const float* X    = (const float*)d_in[0];
    const int*   eidx = (const int*)d_in[1];
    const float* W1s  = (const float*)d_in[2];
    const float* b1s  = (const float*)d_in[3];
    const float* W2s  = (const float*)d_in[4];
    const float* b2s  = (const float*)d_in[5];
    const float* W1d  = (const float*)d_in[6];
    const float* b1d  = (const float*)d_in[7];
    const float* W2d  = (const float*)d_in[8];
    const float* b2d  = (const float*)d_in[9];
    const float* gamma= (const float*)d_in[10];
    float* out = (float*)d_out;

    const int mlp_smem = (128 * SW2 + 128 * SH + 64 * SW1) * (int)sizeof(float);  // 79,872 B
    static bool attr_done = false;
    if (!attr_done) {
        cudaFuncSetAttribute(mlp_kernel, cudaFuncAttributeMaxDynamicSharedMemorySize, mlp_smem);
        attr_done = true;
    }

    dim3 grid1((M_ROWS + 127) / 128, 2, 1);
    mlp_kernel<<<grid1, 256, mlp_smem>>>(X, W1s, b1s, W2s, b2s, W1d, b1d, W2d, b2d);

    const int blocks2 = E_EDGES / EPB;
    edge_kernel<<<blocks2, 512>>>(eidx, gamma, out);
}

// round 16
// speedup vs baseline: 1.1310x; 1.1310x over previous
#include <cuda_runtime.h>
#include <cstddef>
#include <cstdint>

#define N_NODES 50000
#define C_DIM   64
#define HID_DIM 128
#define R_DIM   16
#define B_DIM   2
#define L_DIM   12
#define E_EDGES 1600000
#define T_DIM   8
#define M_ROWS  (B_DIM * N_NODES)   // 100000

// Tables laid out [node][batch][16 floats]: one node = one 128B line.
__device__ __align__(128) float4 g_a[M_ROWS * 4];
__device__ __align__(128) float4 g_b[M_ROWS * 4];

__device__ __forceinline__ uint32_t f2tf(float x) {
    uint32_t r;
    asm("cvt.rna.tf32.f32 %0, %1;" : "=r"(r) : "f"(x));
    return r;
}

__device__ __forceinline__ void mma_tf32(float* d, uint32_t a0, uint32_t a1,
                                         uint32_t a2, uint32_t a3,
                                         uint32_t b0, uint32_t b1) {
    asm volatile(
        "mma.sync.aligned.m16n8k8.row.col.f32.tf32.tf32.f32 "
        "{%0,%1,%2,%3}, {%4,%5,%6,%7}, {%8,%9}, {%0,%1,%2,%3};"
        : "+f"(d[0]), "+f"(d[1]), "+f"(d[2]), "+f"(d[3])
        : "r"(a0), "r"(a1), "r"(a2), "r"(a3), "r"(b0), "r"(b1));
}

// ---------------------------------------------------------------------------
// Kernel 1: tf32 tensor-core MLP — exact R11 version (best measured 44.6us).
// M128 tile, 256 threads, one weight set per blockIdx.y.
// ---------------------------------------------------------------------------
#define SH  68
#define SW1 136
#define SHD 132
#define SW2 20

__global__ __launch_bounds__(256, 2)
void mlp_kernel(const float* __restrict__ X,
                const float* __restrict__ W1s, const float* __restrict__ b1s,
                const float* __restrict__ W2s, const float* __restrict__ b2s,
                const float* __restrict__ W1d, const float* __restrict__ b1d,
                const float* __restrict__ W2d, const float* __restrict__ b2d)
{
    extern __shared__ float sh[];
    float* W2sm = sh;                     // [128][20]
    float* Hsm  = sh + 128 * SW2;         // [128][68]
    float* W1sm = Hsm + 128 * SH;         // [64][136]
    float* Hid  = Hsm;                    // [128][132] alias

    const int tid  = threadIdx.x;
    const int lane = tid & 31;
    const int warp = tid >> 5;
    const int g    = lane >> 2;
    const int t    = lane & 3;
    const int m0   = blockIdx.x * 128;
    const int set  = blockIdx.y;

    const float* W1 = set ? W1d : W1s;
    const float* b1 = set ? b1d : b1s;
    const float* W2 = set ? W2d : W2s;
    const float* b2 = set ? b2d : b2s;
    float4* outTab  = set ? g_b : g_a;

    uint32_t* Hu  = (uint32_t*)Hsm;
    uint32_t* W1u = (uint32_t*)W1sm;
    uint32_t* W2u = (uint32_t*)W2sm;
    uint32_t* Du  = (uint32_t*)Hid;

    #pragma unroll
    for (int u = 0; u < 8; u++) {
        int id = tid + 256 * u;
        int r  = id >> 4, cg = id & 15;
        int m  = m0 + r;
        float4 v = make_float4(0.f, 0.f, 0.f, 0.f);
        if (m < M_ROWS) {
            int b = m / N_NODES;
            int n = m - b * N_NODES;
            v = *(const float4*)&X[(((size_t)b * T_DIM + (T_DIM - 1)) * N_NODES + n) * C_DIM + cg * 4];
        }
        uint4 w; w.x = f2tf(v.x); w.y = f2tf(v.y); w.z = f2tf(v.z); w.w = f2tf(v.w);
        *(uint4*)&Hu[r * SH + cg * 4] = w;
    }
    #pragma unroll
    for (int u = 0; u < 8; u++) {
        int id = tid + 256 * u;
        int k = id >> 5, ng = id & 31;
        float4 v = *(const float4*)&W1[k * 128 + ng * 4];
        uint4 w; w.x = f2tf(v.x); w.y = f2tf(v.y); w.z = f2tf(v.z); w.w = f2tf(v.w);
        *(uint4*)&W1u[k * SW1 + ng * 4] = w;
    }
    #pragma unroll
    for (int u = 0; u < 2; u++) {
        int id = tid + 256 * u;
        int k = id >> 2, rg = id & 3;
        float4 v = *(const float4*)&W2[k * 16 + rg * 4];
        uint4 w; w.x = f2tf(v.x); w.y = f2tf(v.y); w.z = f2tf(v.z); w.w = f2tf(v.w);
        *(uint4*)&W2u[k * SW2 + rg * 4] = w;
    }
    __syncthreads();

    const int mr = warp >> 1;
    const int nc = warp & 1;
    float acc[2][8][4];
    #pragma unroll
    for (int mt = 0; mt < 2; mt++)
        #pragma unroll
        for (int nt = 0; nt < 8; nt++)
            #pragma unroll
            for (int i = 0; i < 4; i++) acc[mt][nt][i] = 0.0f;

    #pragma unroll
    for (int kk = 0; kk < 8; kk++) {
        const int k0 = kk * 8;
        uint32_t a[2][4];
        #pragma unroll
        for (int mt = 0; mt < 2; mt++) {
            int row = mr * 32 + mt * 16;
            a[mt][0] = Hu[(row + g)     * SH + k0 + t];
            a[mt][1] = Hu[(row + g + 8) * SH + k0 + t];
            a[mt][2] = Hu[(row + g)     * SH + k0 + t + 4];
            a[mt][3] = Hu[(row + g + 8) * SH + k0 + t + 4];
        }
        #pragma unroll
        for (int nt = 0; nt < 8; nt++) {
            int n = nc * 64 + nt * 8 + g;
            uint32_t b0 = W1u[(k0 + t)     * SW1 + n];
            uint32_t b1v = W1u[(k0 + t + 4) * SW1 + n];
            mma_tf32(acc[0][nt], a[0][0], a[0][1], a[0][2], a[0][3], b0, b1v);
            mma_tf32(acc[1][nt], a[1][0], a[1][1], a[1][2], a[1][3], b0, b1v);
        }
    }
    __syncthreads();

    #pragma unroll
    for (int nt = 0; nt < 8; nt++) {
        int ncol = nc * 64 + nt * 8 + t * 2;
        float2 bb = __ldg((const float2*)&b1[ncol]);
        #pragma unroll
        for (int mt = 0; mt < 2; mt++) {
            int row = mr * 32 + mt * 16;
            float v0 = acc[mt][nt][0] + bb.x; v0 = v0 > 0.f ? v0 : 0.f;
            float v1 = acc[mt][nt][1] + bb.y; v1 = v1 > 0.f ? v1 : 0.f;
            float v2 = acc[mt][nt][2] + bb.x; v2 = v2 > 0.f ? v2 : 0.f;
            float v3 = acc[mt][nt][3] + bb.y; v3 = v3 > 0.f ? v3 : 0.f;
            uint2 w01; w01.x = f2tf(v0); w01.y = f2tf(v1);
            uint2 w23; w23.x = f2tf(v2); w23.y = f2tf(v3);
            *(uint2*)&Du[(row + g)     * SHD + ncol] = w01;
            *(uint2*)&Du[(row + g + 8) * SHD + ncol] = w23;
        }
    }
    __syncthreads();

    {
        float acc2[2][4];
        #pragma unroll
        for (int nt = 0; nt < 2; nt++)
            #pragma unroll
            for (int i = 0; i < 4; i++) acc2[nt][i] = 0.0f;

        const int rowb = warp * 16;
        #pragma unroll
        for (int kk = 0; kk < 16; kk++) {
            const int k0 = kk * 8;
            uint32_t a0 = Du[(rowb + g)     * SHD + k0 + t];
            uint32_t a1 = Du[(rowb + g + 8) * SHD + k0 + t];
            uint32_t a2 = Du[(rowb + g)     * SHD + k0 + t + 4];
            uint32_t a3 = Du[(rowb + g + 8) * SHD + k0 + t + 4];
            #pragma unroll
            for (int nt = 0; nt < 2; nt++) {
                uint32_t b0 = W2u[(k0 + t)     * SW2 + nt * 8 + g];
                uint32_t b1v = W2u[(k0 + t + 4) * SW2 + nt * 8 + g];
                mma_tf32(acc2[nt], a0, a1, a2, a3, b0, b1v);
            }
        }

        #pragma unroll
        for (int nt = 0; nt < 2; nt++) {
            int r0 = nt * 8 + t * 2;
            float2 bb = __ldg((const float2*)&b2[r0]);
            int m = m0 + rowb + g;
            if (m < M_ROWS) {
                int b = m / N_NODES, n = m - b * N_NODES;
                float2 v; v.x = acc2[nt][0] + bb.x; v.y = acc2[nt][1] + bb.y;
                *(float2*)((float*)outTab + ((size_t)n * 2 + b) * 16 + r0) = v;
            }
            m = m0 + rowb + g + 8;
            if (m < M_ROWS) {
                int b = m / N_NODES, n = m - b * N_NODES;
                float2 v; v.x = acc2[nt][2] + bb.x; v.y = acc2[nt][3] + bb.y;
                *(float2*)((float*)outTab + ((size_t)n * 2 + b) * 16 + r0) = v;
            }
        }
    }
}

// ---------------------------------------------------------------------------
// Kernel 2: edge scoring — exact R11 structure (measured 62.0us), with
// launch_bounds(256, 5) to lift occupancy 4 -> 5 CTAs/SM (latency-bound).
// ---------------------------------------------------------------------------
#define EPB 256
#define PSTRIDE 9     // float4 per edge in p-stage (8 + 1 pad)

__global__ __launch_bounds__(256, 5)
void edge_kernel(const int* __restrict__ eidx,
                 const float* __restrict__ gamma,
                 float* __restrict__ out)
{
    __shared__ float4 pst[EPB * PSTRIDE];    // 36,864 B
    __shared__ int    sIJ[2 * EPB];
    __shared__ float  g[L_DIM * R_DIM];

    const int tid = threadIdx.x;
    const long long e0 = (long long)blockIdx.x * EPB;

    sIJ[tid]       = eidx[e0 + tid];
    sIJ[tid + EPB] = eidx[(size_t)E_EDGES + e0 + tid];
    if (tid < L_DIM * R_DIM) g[tid] = gamma[tid];
    __syncthreads();

    // Fused gather+product: 2048 (edge,sub) pairs, 8 per thread.
    {
        float4 pr[8];
        int    dst[8];
        #pragma unroll
        for (int u = 0; u < 8; u++) {
            int gid  = tid + 256 * u;
            int edge = gid >> 3;
            int sub  = gid & 7;            // bb*4 + q
            int nI   = sIJ[edge];
            int nJ   = sIJ[EPB + edge];
            float4 av = g_a[(size_t)nI * 8 + sub];
            float4 bv = g_b[(size_t)nJ * 8 + sub];
            float4 p;
            p.x = av.x * bv.x; p.y = av.y * bv.y;
            p.z = av.z * bv.z; p.w = av.w * bv.w;
            pr[u]  = p;
            dst[u] = edge * PSTRIDE + sub;
        }
        #pragma unroll
        for (int u = 0; u < 8; u++) pst[dst[u]] = pr[u];
    }
    __syncthreads();

    // Compute: thread = edge, both batches; streaming stores.
    {
        const float4* base = pst + tid * PSTRIDE;
        float p0[16], p1[16];
        #pragma unroll
        for (int q = 0; q < 4; q++) {
            float4 v0 = base[q];
            float4 v1 = base[4 + q];
            p0[q * 4 + 0] = v0.x; p0[q * 4 + 1] = v0.y;
            p0[q * 4 + 2] = v0.z; p0[q * 4 + 3] = v0.w;
            p1[q * 4 + 0] = v1.x; p1[q * 4 + 1] = v1.y;
            p1[q * 4 + 2] = v1.z; p1[q * 4 + 3] = v1.w;
        }

        float* o0 = out + e0 + tid;
        float* o1 = out + (size_t)L_DIM * E_EDGES + e0 + tid;
        #pragma unroll
        for (int l = 0; l < L_DIM; l++) {
            const float4* gr = (const float4*)&g[l * R_DIM];
            float4 g0 = gr[0], g1 = gr[1], g2 = gr[2], g3 = gr[3];
            float s0 = g0.x * p0[0]  + g0.y * p0[1]  + g0.z * p0[2]  + g0.w * p0[3]
                     + g1.x * p0[4]  + g1.y * p0[5]  + g1.z * p0[6]  + g1.w * p0[7]
                     + g2.x * p0[8]  + g2.y * p0[9]  + g2.z * p0[10] + g2.w * p0[11]
                     + g3.x * p0[12] + g3.y * p0[13] + g3.z * p0[14] + g3.w * p0[15];
            float s1 = g0.x * p1[0]  + g0.y * p1[1]  + g0.z * p1[2]  + g0.w * p1[3]
                     + g1.x * p1[4]  + g1.y * p1[5]  + g1.z * p1[6]  + g1.w * p1[7]
                     + g2.x * p1[8]  + g2.y * p1[9]  + g2.z * p1[10] + g2.w * p1[11]
                     + g3.x * p1[12] + g3.y * p1[13] + g3.z * p1[14] + g3.w * p1[15];
            __stcs(o0 + (size_t)l * E_EDGES, s0);
            __stcs(o1 + (size_t)l * E_EDGES, s1);
        }
    }
}

// ---------------------------------------------------------------------------
// Launch
// ---------------------------------------------------------------------------
extern "C" void kernel_launch(void* const* d_in, const int* in_sizes, int n_in,
                              void* d_out, int out_size)
{
    const float* X    = (const float*)d_in[0];
    const int*   eidx = (const int*)d_in[1];
    const float* W1s  = (const float*)d_in[2];
    const float* b1s  = (const float*)d_in[3];
    const float* W2s  = (const float*)d_in[4];
    const float* b2s  = (const float*)d_in[5];
    const float* W1d  = (const float*)d_in[6];
    const float* b1d  = (const float*)d_in[7];
    const float* W2d  = (const float*)d_in[8];
    const float* b2d  = (const float*)d_in[9];
    const float* gamma= (const float*)d_in[10];
    float* out = (float*)d_out;

    const int mlp_smem = (128 * SW2 + 128 * SH + 64 * SW1) * (int)sizeof(float);  // 79,872 B
    static bool attr_done = false;
    if (!attr_done) {
        cudaFuncSetAttribute(mlp_kernel, cudaFuncAttributeMaxDynamicSharedMemorySize, mlp_smem);
        attr_done = true;
    }

    dim3 grid1((M_ROWS + 127) / 128, 2, 1);
    mlp_kernel<<<grid1, 256, mlp_smem>>>(X, W1s, b1s, W2s, b2s, W1d, b1d, W2d, b2d);

    const int blocks2 = E_EDGES / EPB;
    edge_kernel<<<blocks2, 256>>>(eidx, gamma, out);
}

// round 17
// speedup vs baseline: 1.2029x; 1.0636x over previous
#include <cuda_runtime.h>
#include <cstddef>
#include <cstdint>

#define N_NODES 50000
#define C_DIM   64
#define HID_DIM 128
#define R_DIM   16
#define B_DIM   2
#define L_DIM   12
#define E_EDGES 1600000
#define T_DIM   8
#define M_ROWS  (B_DIM * N_NODES)   // 100000

// Tables laid out [node][batch][16 floats]: one node = one 128B line.
__device__ __align__(128) float4 g_a[M_ROWS * 4];
__device__ __align__(128) float4 g_b[M_ROWS * 4];

__device__ __forceinline__ uint32_t f2tf(float x) {
    uint32_t r;
    asm("cvt.rna.tf32.f32 %0, %1;" : "=r"(r) : "f"(x));
    return r;
}

__device__ __forceinline__ void mma_tf32(float* d, uint32_t a0, uint32_t a1,
                                         uint32_t a2, uint32_t a3,
                                         uint32_t b0, uint32_t b1) {
    asm volatile(
        "mma.sync.aligned.m16n8k8.row.col.f32.tf32.tf32.f32 "
        "{%0,%1,%2,%3}, {%4,%5,%6,%7}, {%8,%9}, {%0,%1,%2,%3};"
        : "+f"(d[0]), "+f"(d[1]), "+f"(d[2]), "+f"(d[3])
        : "r"(a0), "r"(a1), "r"(a2), "r"(a3), "r"(b0), "r"(b1));
}

// ---------------------------------------------------------------------------
// Kernel 1: tf32 tensor-core MLP — exact R11 version (best measured 44.6us).
// M128 tile, 256 threads, one weight set per blockIdx.y.
// ---------------------------------------------------------------------------
#define SH  68
#define SW1 136
#define SHD 132
#define SW2 20

__global__ __launch_bounds__(256, 2)
void mlp_kernel(const float* __restrict__ X,
                const float* __restrict__ W1s, const float* __restrict__ b1s,
                const float* __restrict__ W2s, const float* __restrict__ b2s,
                const float* __restrict__ W1d, const float* __restrict__ b1d,
                const float* __restrict__ W2d, const float* __restrict__ b2d)
{
    extern __shared__ float sh[];
    float* W2sm = sh;                     // [128][20]
    float* Hsm  = sh + 128 * SW2;         // [128][68]
    float* W1sm = Hsm + 128 * SH;         // [64][136]
    float* Hid  = Hsm;                    // [128][132] alias

    const int tid  = threadIdx.x;
    const int lane = tid & 31;
    const int warp = tid >> 5;
    const int g    = lane >> 2;
    const int t    = lane & 3;
    const int m0   = blockIdx.x * 128;
    const int set  = blockIdx.y;

    const float* W1 = set ? W1d : W1s;
    const float* b1 = set ? b1d : b1s;
    const float* W2 = set ? W2d : W2s;
    const float* b2 = set ? b2d : b2s;
    float4* outTab  = set ? g_b : g_a;

    uint32_t* Hu  = (uint32_t*)Hsm;
    uint32_t* W1u = (uint32_t*)W1sm;
    uint32_t* W2u = (uint32_t*)W2sm;
    uint32_t* Du  = (uint32_t*)Hid;

    #pragma unroll
    for (int u = 0; u < 8; u++) {
        int id = tid + 256 * u;
        int r  = id >> 4, cg = id & 15;
        int m  = m0 + r;
        float4 v = make_float4(0.f, 0.f, 0.f, 0.f);
        if (m < M_ROWS) {
            int b = m / N_NODES;
            int n = m - b * N_NODES;
            v = *(const float4*)&X[(((size_t)b * T_DIM + (T_DIM - 1)) * N_NODES + n) * C_DIM + cg * 4];
        }
        uint4 w; w.x = f2tf(v.x); w.y = f2tf(v.y); w.z = f2tf(v.z); w.w = f2tf(v.w);
        *(uint4*)&Hu[r * SH + cg * 4] = w;
    }
    #pragma unroll
    for (int u = 0; u < 8; u++) {
        int id = tid + 256 * u;
        int k = id >> 5, ng = id & 31;
        float4 v = *(const float4*)&W1[k * 128 + ng * 4];
        uint4 w; w.x = f2tf(v.x); w.y = f2tf(v.y); w.z = f2tf(v.z); w.w = f2tf(v.w);
        *(uint4*)&W1u[k * SW1 + ng * 4] = w;
    }
    #pragma unroll
    for (int u = 0; u < 2; u++) {
        int id = tid + 256 * u;
        int k = id >> 2, rg = id & 3;
        float4 v = *(const float4*)&W2[k * 16 + rg * 4];
        uint4 w; w.x = f2tf(v.x); w.y = f2tf(v.y); w.z = f2tf(v.z); w.w = f2tf(v.w);
        *(uint4*)&W2u[k * SW2 + rg * 4] = w;
    }
    __syncthreads();

    const int mr = warp >> 1;
    const int nc = warp & 1;
    float acc[2][8][4];
    #pragma unroll
    for (int mt = 0; mt < 2; mt++)
        #pragma unroll
        for (int nt = 0; nt < 8; nt++)
            #pragma unroll
            for (int i = 0; i < 4; i++) acc[mt][nt][i] = 0.0f;

    #pragma unroll
    for (int kk = 0; kk < 8; kk++) {
        const int k0 = kk * 8;
        uint32_t a[2][4];
        #pragma unroll
        for (int mt = 0; mt < 2; mt++) {
            int row = mr * 32 + mt * 16;
            a[mt][0] = Hu[(row + g)     * SH + k0 + t];
            a[mt][1] = Hu[(row + g + 8) * SH + k0 + t];
            a[mt][2] = Hu[(row + g)     * SH + k0 + t + 4];
            a[mt][3] = Hu[(row + g + 8) * SH + k0 + t + 4];
        }
        #pragma unroll
        for (int nt = 0; nt < 8; nt++) {
            int n = nc * 64 + nt * 8 + g;
            uint32_t b0 = W1u[(k0 + t)     * SW1 + n];
            uint32_t b1v = W1u[(k0 + t + 4) * SW1 + n];
            mma_tf32(acc[0][nt], a[0][0], a[0][1], a[0][2], a[0][3], b0, b1v);
            mma_tf32(acc[1][nt], a[1][0], a[1][1], a[1][2], a[1][3], b0, b1v);
        }
    }
    __syncthreads();

    #pragma unroll
    for (int nt = 0; nt < 8; nt++) {
        int ncol = nc * 64 + nt * 8 + t * 2;
        float2 bb = __ldg((const float2*)&b1[ncol]);
        #pragma unroll
        for (int mt = 0; mt < 2; mt++) {
            int row = mr * 32 + mt * 16;
            float v0 = acc[mt][nt][0] + bb.x; v0 = v0 > 0.f ? v0 : 0.f;
            float v1 = acc[mt][nt][1] + bb.y; v1 = v1 > 0.f ? v1 : 0.f;
            float v2 = acc[mt][nt][2] + bb.x; v2 = v2 > 0.f ? v2 : 0.f;
            float v3 = acc[mt][nt][3] + bb.y; v3 = v3 > 0.f ? v3 : 0.f;
            uint2 w01; w01.x = f2tf(v0); w01.y = f2tf(v1);
            uint2 w23; w23.x = f2tf(v2); w23.y = f2tf(v3);
            *(uint2*)&Du[(row + g)     * SHD + ncol] = w01;
            *(uint2*)&Du[(row + g + 8) * SHD + ncol] = w23;
        }
    }
    __syncthreads();

    {
        float acc2[2][4];
        #pragma unroll
        for (int nt = 0; nt < 2; nt++)
            #pragma unroll
            for (int i = 0; i < 4; i++) acc2[nt][i] = 0.0f;

        const int rowb = warp * 16;
        #pragma unroll
        for (int kk = 0; kk < 16; kk++) {
            const int k0 = kk * 8;
            uint32_t a0 = Du[(rowb + g)     * SHD + k0 + t];
            uint32_t a1 = Du[(rowb + g + 8) * SHD + k0 + t];
            uint32_t a2 = Du[(rowb + g)     * SHD + k0 + t + 4];
            uint32_t a3 = Du[(rowb + g + 8) * SHD + k0 + t + 4];
            #pragma unroll
            for (int nt = 0; nt < 2; nt++) {
                uint32_t b0 = W2u[(k0 + t)     * SW2 + nt * 8 + g];
                uint32_t b1v = W2u[(k0 + t + 4) * SW2 + nt * 8 + g];
                mma_tf32(acc2[nt], a0, a1, a2, a3, b0, b1v);
            }
        }

        #pragma unroll
        for (int nt = 0; nt < 2; nt++) {
            int r0 = nt * 8 + t * 2;
            float2 bb = __ldg((const float2*)&b2[r0]);
            int m = m0 + rowb + g;
            if (m < M_ROWS) {
                int b = m / N_NODES, n = m - b * N_NODES;
                float2 v; v.x = acc2[nt][0] + bb.x; v.y = acc2[nt][1] + bb.y;
                *(float2*)((float*)outTab + ((size_t)n * 2 + b) * 16 + r0) = v;
            }
            m = m0 + rowb + g + 8;
            if (m < M_ROWS) {
                int b = m / N_NODES, n = m - b * N_NODES;
                float2 v; v.x = acc2[nt][2] + bb.x; v.y = acc2[nt][3] + bb.y;
                *(float2*)((float*)outTab + ((size_t)n * 2 + b) * 16 + r0) = v;
            }
        }
    }
}

// ---------------------------------------------------------------------------
// Kernel 2: edge scoring. EPB=512, 256 threads; fused product-gather
// (R11-proven pattern), then compute phase handles TWO edges per thread
// inside the same l-iteration so each gamma float4 feeds 64 FMAs (gamma
// L1-broadcast wavefronts halve: 1.5 -> 0.75 wf/edge). Dyn smem 78.6KB.
// ---------------------------------------------------------------------------
#define EPB 512
#define PSTRIDE 9     // float4 per edge in p-stage (8 + 1 pad)

__global__ __launch_bounds__(256)
void edge_kernel(const int* __restrict__ eidx,
                 const float* __restrict__ gamma,
                 float* __restrict__ out)
{
    extern __shared__ float4 esh[];
    float4* pst = esh;                               // [EPB][9]   73,728 B
    int*    sIJ = (int*)(esh + EPB * PSTRIDE);       // [2][EPB]    4,096 B
    float*  g   = (float*)(sIJ + 2 * EPB);           // [12][16]      768 B

    const int tid = threadIdx.x;
    const long long e0 = (long long)blockIdx.x * EPB;

    #pragma unroll
    for (int w = 0; w < 4; w++) {
        int idx = tid + 256 * w;
        sIJ[idx] = (idx < EPB) ? eidx[e0 + idx]
                               : eidx[(size_t)E_EDGES + e0 + (idx - EPB)];
    }
    if (tid < L_DIM * R_DIM) g[tid] = gamma[tid];
    __syncthreads();

    // Fused gather+product: 4096 (edge,sub) pairs, 16 per thread, 2 rounds.
    #pragma unroll
    for (int rnd = 0; rnd < 2; rnd++) {
        float4 pr[8];
        int    dst[8];
        #pragma unroll
        for (int u = 0; u < 8; u++) {
            int gid  = tid + 256 * (rnd * 8 + u);
            int edge = gid >> 3;
            int sub  = gid & 7;            // bb*4 + q
            int nI   = sIJ[edge];
            int nJ   = sIJ[EPB + edge];
            float4 av = g_a[(size_t)nI * 8 + sub];
            float4 bv = g_b[(size_t)nJ * 8 + sub];
            float4 p;
            p.x = av.x * bv.x; p.y = av.y * bv.y;
            p.z = av.z * bv.z; p.w = av.w * bv.w;
            pr[u]  = p;
            dst[u] = edge * PSTRIDE + sub;
        }
        #pragma unroll
        for (int u = 0; u < 8; u++) pst[dst[u]] = pr[u];
    }
    __syncthreads();

    // Compute: thread handles edges (tid) and (tid+256), both batches,
    // sharing each gamma load across all four streams.
    {
        const float4* baseA = pst + tid * PSTRIDE;
        const float4* baseB = pst + (tid + 256) * PSTRIDE;

        float pa0[16], pa1[16], pb0[16], pb1[16];
        #pragma unroll
        for (int q = 0; q < 4; q++) {
            float4 v;
            v = baseA[q];
            pa0[q*4+0] = v.x; pa0[q*4+1] = v.y; pa0[q*4+2] = v.z; pa0[q*4+3] = v.w;
            v = baseA[4+q];
            pa1[q*4+0] = v.x; pa1[q*4+1] = v.y; pa1[q*4+2] = v.z; pa1[q*4+3] = v.w;
            v = baseB[q];
            pb0[q*4+0] = v.x; pb0[q*4+1] = v.y; pb0[q*4+2] = v.z; pb0[q*4+3] = v.w;
            v = baseB[4+q];
            pb1[q*4+0] = v.x; pb1[q*4+1] = v.y; pb1[q*4+2] = v.z; pb1[q*4+3] = v.w;
        }

        float* oa0 = out + e0 + tid;
        float* oa1 = out + (size_t)L_DIM * E_EDGES + e0 + tid;
        float* ob0 = out + e0 + tid + 256;
        float* ob1 = out + (size_t)L_DIM * E_EDGES + e0 + tid + 256;

        #pragma unroll
        for (int l = 0; l < L_DIM; l++) {
            const float4* gr = (const float4*)&g[l * R_DIM];
            float4 g0 = gr[0], g1 = gr[1], g2 = gr[2], g3 = gr[3];

            float sa0 = g0.x*pa0[0]  + g0.y*pa0[1]  + g0.z*pa0[2]  + g0.w*pa0[3]
                      + g1.x*pa0[4]  + g1.y*pa0[5]  + g1.z*pa0[6]  + g1.w*pa0[7]
                      + g2.x*pa0[8]  + g2.y*pa0[9]  + g2.z*pa0[10] + g2.w*pa0[11]
                      + g3.x*pa0[12] + g3.y*pa0[13] + g3.z*pa0[14] + g3.w*pa0[15];
            float sa1 = g0.x*pa1[0]  + g0.y*pa1[1]  + g0.z*pa1[2]  + g0.w*pa1[3]
                      + g1.x*pa1[4]  + g1.y*pa1[5]  + g1.z*pa1[6]  + g1.w*pa1[7]
                      + g2.x*pa1[8]  + g2.y*pa1[9]  + g2.z*pa1[10] + g2.w*pa1[11]
                      + g3.x*pa1[12] + g3.y*pa1[13] + g3.z*pa1[14] + g3.w*pa1[15];
            float sb0 = g0.x*pb0[0]  + g0.y*pb0[1]  + g0.z*pb0[2]  + g0.w*pb0[3]
                      + g1.x*pb0[4]  + g1.y*pb0[5]  + g1.z*pb0[6]  + g1.w*pb0[7]
                      + g2.x*pb0[8]  + g2.y*pb0[9]  + g2.z*pb0[10] + g2.w*pb0[11]
                      + g3.x*pb0[12] + g3.y*pb0[13] + g3.z*pb0[14] + g3.w*pb0[15];
            float sb1 = g0.x*pb1[0]  + g0.y*pb1[1]  + g0.z*pb1[2]  + g0.w*pb1[3]
                      + g1.x*pb1[4]  + g1.y*pb1[5]  + g1.z*pb1[6]  + g1.w*pb1[7]
                      + g2.x*pb1[8]  + g2.y*pb1[9]  + g2.z*pb1[10] + g2.w*pb1[11]
                      + g3.x*pb1[12] + g3.y*pb1[13] + g3.z*pb1[14] + g3.w*pb1[15];

            __stcs(oa0 + (size_t)l * E_EDGES, sa0);
            __stcs(oa1 + (size_t)l * E_EDGES, sa1);
            __stcs(ob0 + (size_t)l * E_EDGES, sb0);
            __stcs(ob1 + (size_t)l * E_EDGES, sb1);
        }
    }
}

// ---------------------------------------------------------------------------
// Launch
// ---------------------------------------------------------------------------
extern "C" void kernel_launch(void* const* d_in, const int* in_sizes, int n_in,
                              void* d_out, int out_size)
{
    const float* X    = (const float*)d_in[0];
    const int*   eidx = (const int*)d_in[1];
    const float* W1s  = (const float*)d_in[2];
    const float* b1s  = (const float*)d_in[3];
    const float* W2s  = (const float*)d_in[4];
    const float* b2s  = (const float*)d_in[5];
    const float* W1d  = (const float*)d_in[6];
    const float* b1d  = (const float*)d_in[7];
    const float* W2d  = (const float*)d_in[8];
    const float* b2d  = (const float*)d_in[9];
    const float* gamma= (const float*)d_in[10];
    float* out = (float*)d_out;

    const int mlp_smem  = (128 * SW2 + 128 * SH + 64 * SW1) * (int)sizeof(float); // 79,872 B
    const int edge_smem = EPB * PSTRIDE * 16 + 2 * EPB * (int)sizeof(int)
                          + L_DIM * R_DIM * (int)sizeof(float);                    // 78,592 B
    static bool attr_done = false;
    if (!attr_done) {
        cudaFuncSetAttribute(mlp_kernel,  cudaFuncAttributeMaxDynamicSharedMemorySize, mlp_smem);
        cudaFuncSetAttribute(edge_kernel, cudaFuncAttributeMaxDynamicSharedMemorySize, edge_smem);
        attr_done = true;
    }

    dim3 grid1((M_ROWS + 127) / 128, 2, 1);
    mlp_kernel<<<grid1, 256, mlp_smem>>>(X, W1s, b1s, W2s, b2s, W1d, b1d, W2d, b2d);

    const int blocks2 = E_EDGES / EPB;
    edge_kernel<<<blocks2, 256, edge_smem>>>(eidx, gamma, out);
}